// round 1
// baseline (speedup 1.0000x reference)
#include <cuda_runtime.h>

// Problem constants (fixed shapes for SNNModel_67611375174158)
#define B_DIM   128
#define T_DIM   128
#define BT      (B_DIM * T_DIM)          // 16384 rows
#define NIN     2312                     // 2*34*34
#define NCH     (NIN / 4)                // 578 int4 chunks per row
#define NFULL   (NCH / 32)               // 18 full 32-chunk groups
#define NHID    2048
#define NOUT    10
#define ALPHA_F 0.001f

// Scratch (no allocations allowed -> __device__ globals)
__device__ unsigned int g_accAny[BT];    // bits[3:0]=acc0&15, bit8=row-has-any-spike
__device__ unsigned int g_P[16];         // bit-plane patterns P[e*4+k] (e: word-in-int4, k: nibble bit)
__device__ int          g_uniform;       // 1 if id nibbles are 128-periodic (fast path valid)
__device__ int          g_s1v[BT];       // s1 state after step (b,t), -1 if timestep inactive
__device__ int          g_c0[16];        // histogram of s0 over active events
__device__ int          g_c1[16];        // histogram of s1 over active events

// ---------------------------------------------------------------------------
// Setup: build ballot bit-plane patterns from input_neuron_id, check whether
// the fold-across-groups fast path is valid (nibbles 128-periodic).
// ---------------------------------------------------------------------------
__global__ void k_setup(const int* __restrict__ ids) {
    int tid = threadIdx.x;
    if (tid < 32) {
        #pragma unroll
        for (int e = 0; e < 4; e++) {
            int i = 4 * tid + e;                         // element position within a 128-group
            int nib = (i < NIN) ? (ids[i] & 15) : 0;
            #pragma unroll
            for (int k = 0; k < 4; k++) {
                unsigned m = __ballot_sync(0xFFFFFFFFu, (nib >> k) & 1);
                if (tid == 0) g_P[e * 4 + k] = m;
            }
        }
        if (tid == 0) g_uniform = 1;
    }
    __syncthreads();
    int ok = 1;
    for (int i = tid; i < NIN; i += blockDim.x)
        if ((ids[i] & 15) != (ids[i & 127] & 15)) ok = 0;
    if (!ok) atomicAnd(&g_uniform, 0);
}

// ---------------------------------------------------------------------------
// Main memory-bound kernel: one warp per (b,t) row of frames (2312 int32).
// Computes acc0[b,t] = XOR of (id&15) over active inputs, and any-spike flag.
// Fast path: ballot masks XOR-folded across groups (parity is GF(2)-linear),
// 4 popcounts per row at the end. ~17 warp-instructions per 512B loaded.
// ---------------------------------------------------------------------------
__global__ void __launch_bounds__(256) k_rowacc(const int* __restrict__ frames,
                                                const int* __restrict__ ids) {
    int wid  = (blockIdx.x * blockDim.x + threadIdx.x) >> 5;
    int lane = threadIdx.x & 31;
    if (wid >= BT) return;

    const int* rowp = frames + (size_t)wid * NIN;
    unsigned acc, anyflag;

    if (g_uniform) {
        const int4* row4 = reinterpret_cast<const int4*>(rowp);
        unsigned m0 = 0, m1 = 0, m2 = 0, m3 = 0, anym = 0;
        #pragma unroll 3
        for (int g = 0; g < NFULL; g++) {
            int4 v = __ldg(&row4[g * 32 + lane]);
            unsigned b0 = __ballot_sync(0xFFFFFFFFu, v.x != 0);
            unsigned b1 = __ballot_sync(0xFFFFFFFFu, v.y != 0);
            unsigned b2 = __ballot_sync(0xFFFFFFFFu, v.z != 0);
            unsigned b3 = __ballot_sync(0xFFFFFFFFu, v.w != 0);
            m0 ^= b0; m1 ^= b1; m2 ^= b2; m3 ^= b3;
            anym |= b0 | b1 | b2 | b3;
        }
        {   // tail: chunks [NFULL*32, NCH) — group base is 128-aligned so phases match
            int c = NFULL * 32 + lane;
            int4 v = make_int4(0, 0, 0, 0);
            if (c < NCH) v = __ldg(&row4[c]);
            unsigned b0 = __ballot_sync(0xFFFFFFFFu, v.x != 0);
            unsigned b1 = __ballot_sync(0xFFFFFFFFu, v.y != 0);
            unsigned b2 = __ballot_sync(0xFFFFFFFFu, v.z != 0);
            unsigned b3 = __ballot_sync(0xFFFFFFFFu, v.w != 0);
            m0 ^= b0; m1 ^= b1; m2 ^= b2; m3 ^= b3;
            anym |= b0 | b1 | b2 | b3;
        }
        unsigned a = 0;
        #pragma unroll
        for (int k = 0; k < 4; k++) {
            unsigned par = (__popc(m0 & g_P[0 * 4 + k]) + __popc(m1 & g_P[1 * 4 + k]) +
                            __popc(m2 & g_P[2 * 4 + k]) + __popc(m3 & g_P[3 * 4 + k])) & 1u;
            a |= par << k;
        }
        acc = a;
        anyflag = (anym != 0u) ? 1u : 0u;
    } else {
        // Correct general fallback (never taken for the actual data)
        unsigned x = 0, any = 0;
        for (int i = lane; i < NIN; i += 32) {
            int v = __ldg(&rowp[i]);
            if (v) { x ^= (unsigned)(__ldg(&ids[i]) & 15); any = 1u; }
        }
        #pragma unroll
        for (int o = 16; o; o >>= 1) {
            x   ^= __shfl_xor_sync(0xFFFFFFFFu, x, o);
            any |= __shfl_xor_sync(0xFFFFFFFFu, any, o);
        }
        acc = x & 15u;
        anyflag = any;
    }

    if (lane == 0) g_accAny[wid] = acc | (anyflag << 8);
}

// ---------------------------------------------------------------------------
// Sequential scan (single block): A1 table, has[t], delta_t sequence,
// per-batch 4-bit state recurrences, s1 trace, 16-bin histograms.
// ---------------------------------------------------------------------------
__global__ void __launch_bounds__(256) k_scan(const int*   __restrict__ nid0,
                                              const float* __restrict__ vth0,
                                              const float* __restrict__ map0) {
    __shared__ int           sA1[16];
    __shared__ int           sc0[16], sc1[16];
    __shared__ unsigned char sHas[T_DIM];
    __shared__ unsigned char sDt[T_DIM];

    int tid = threadIdx.x;
    if (tid < 16) { sA1[tid] = 0; sc0[tid] = 0; sc1[tid] = 0; }
    __syncthreads();

    // A1[p] = XOR_{j: mem_map0[j,p] >= v_th0[j]} neuron_id0[j]
    {
        int loc[16];
        #pragma unroll
        for (int p = 0; p < 16; p++) loc[p] = 0;
        for (int j = tid; j < NHID; j += 256) {
            int   nid = __ldg(&nid0[j]);
            float vt  = __ldg(&vth0[j]);
            const float4* r = reinterpret_cast<const float4*>(map0 + (size_t)j * 16);
            #pragma unroll
            for (int q = 0; q < 4; q++) {
                float4 mv = __ldg(&r[q]);
                if (mv.x >= vt) loc[q * 4 + 0] ^= nid;
                if (mv.y >= vt) loc[q * 4 + 1] ^= nid;
                if (mv.z >= vt) loc[q * 4 + 2] ^= nid;
                if (mv.w >= vt) loc[q * 4 + 3] ^= nid;
            }
        }
        #pragma unroll
        for (int p = 0; p < 16; p++)
            if (loc[p]) atomicXor(&sA1[p], loc[p]);
    }

    // has[t] = OR over batch of per-row any-spike flags
    if (tid < T_DIM) {
        unsigned any = 0;
        for (int b = 0; b < B_DIM; b++) any |= g_accAny[b * T_DIM + tid];
        sHas[tid] = (unsigned char)((any >> 8) & 1u);
    }
    __syncthreads();

    // delta_t sequence (t_last is a global scalar in the reference)
    if (tid == 0) {
        int tl = 0;
        for (int t = 0; t < T_DIM; t++) {
            if (sHas[t]) { sDt[t] = (unsigned char)((t - tl) & 15); tl = t; }
            else         { sDt[t] = 0; }
        }
    }
    __syncthreads();

    // Per-batch 4-bit state scan + packed byte histograms
    if (tid < B_DIM) {
        int base = tid * T_DIM;
        int s0 = 0, s1 = 0;
        unsigned long long h0lo = 0, h0hi = 0, h1lo = 0, h1hi = 0;
        for (int t = 0; t < T_DIM; t++) {
            if (sHas[t]) {
                int dt = sDt[t];
                int a  = (int)(g_accAny[base + t] & 15u);
                s0 ^= dt ^ a;                       // stays in [0,16)
                {
                    unsigned long long inc = 1ULL << ((s0 & 7) * 8);
                    if (s0 < 8) h0lo += inc; else h0hi += inc;
                }
                int a1 = sA1[s0] & 15;
                s1 ^= dt ^ a1;
                {
                    unsigned long long inc = 1ULL << ((s1 & 7) * 8);
                    if (s1 < 8) h1lo += inc; else h1hi += inc;
                }
                g_s1v[base + t] = s1;
            } else {
                g_s1v[base + t] = -1;
            }
        }
        #pragma unroll
        for (int p = 0; p < 8; p++) {
            int c;
            c = (int)((h0lo >> (p * 8)) & 255u); if (c) atomicAdd(&sc0[p],     c);
            c = (int)((h0hi >> (p * 8)) & 255u); if (c) atomicAdd(&sc0[p + 8], c);
            c = (int)((h1lo >> (p * 8)) & 255u); if (c) atomicAdd(&sc1[p],     c);
            c = (int)((h1hi >> (p * 8)) & 255u); if (c) atomicAdd(&sc1[p + 8], c);
        }
    }
    __syncthreads();
    if (tid < 16) { g_c0[tid] = sc0[tid]; g_c1[tid] = sc1[tid]; }
}

// ---------------------------------------------------------------------------
// Parallel epilogue: fill out_spikes [BT,10], d0 [2048,16], d1 [10,16]
// ---------------------------------------------------------------------------
__global__ void __launch_bounds__(256) k_out(float*       __restrict__ out,
                                             const float* __restrict__ map0,
                                             const float* __restrict__ map1,
                                             const float* __restrict__ vth1) {
    const int NS = BT * NOUT;
    int e = blockIdx.x * blockDim.x + threadIdx.x;
    if (e < NS) {
        int bt = e / NOUT;
        int k  = e - bt * NOUT;
        int s  = g_s1v[bt];
        float r = 0.0f;
        if (s >= 0)
            r = (__ldg(&map1[k * 16 + s]) >= __ldg(&vth1[k])) ? 1.0f : 0.0f;
        out[e] = r;
    } else if (e < NS + NHID * 16) {
        int f = e - NS;
        int p = f & 15;
        out[e] = ALPHA_F * (float)g_c0[p] * ((float)p - __ldg(&map0[f]));
    } else if (e < NS + NHID * 16 + NOUT * 16) {
        int f = e - NS - NHID * 16;
        int p = f & 15;
        out[e] = ALPHA_F * (float)g_c1[p] * ((float)p - __ldg(&map1[f]));
    }
}

// ---------------------------------------------------------------------------
// Inputs (metadata order): frames, input_neuron_id, tau0, v_th0, neuron_id0,
// mem_map0, syn_w0, tau1, v_th1, neuron_id1, mem_map1, syn_w1
// ---------------------------------------------------------------------------
extern "C" void kernel_launch(void* const* d_in, const int* in_sizes, int n_in,
                              void* d_out, int out_size) {
    const int*   frames = (const int*)  d_in[0];
    const int*   inid   = (const int*)  d_in[1];
    const float* vth0   = (const float*)d_in[3];
    const int*   nid0   = (const int*)  d_in[4];
    const float* map0   = (const float*)d_in[5];
    const float* vth1   = (const float*)d_in[8];
    const float* map1   = (const float*)d_in[10];

    k_setup<<<1, 128>>>(inid);
    k_rowacc<<<(BT * 32 + 255) / 256, 256>>>(frames, inid);
    k_scan<<<1, 256>>>(nid0, vth0, map0);

    const int TOT = BT * NOUT + NHID * 16 + NOUT * 16;
    k_out<<<(TOT + 255) / 256, 256>>>((float*)d_out, map0, map1, vth1);
}

// round 2
// speedup vs baseline: 1.1317x; 1.1317x over previous
#include <cuda_runtime.h>

// Problem constants (fixed shapes for SNNModel_67611375174158)
#define B_DIM   128
#define T_DIM   128
#define BT      (B_DIM * T_DIM)          // 16384 rows
#define NIN     2312                     // 2*34*34
#define NCH     (NIN / 4)                // 578 int4 chunks per row
#define NFULL   (NCH / 32)               // 18 full 32-chunk groups
#define NTAIL   (NCH - NFULL * 32)       // 2 tail chunks
#define NHID    2048
#define NOUT    10
#define ALPHA_F 0.001f

#define NS_OUT  (BT * NOUT)                       // 163840 spike floats
#define TOT_OUT (NS_OUT + NHID * 16 + NOUT * 16)  // 196768 total floats
#define NB_FUSED 32
#define CHUNK   ((TOT_OUT + NB_FUSED - 1) / NB_FUSED)   // 6149 (exact: 32*6149=196768)

// Scratch (no allocations allowed -> __device__ globals)
__device__ unsigned char g_accAnyT[BT];  // [t*128+b]: bits[3:0]=acc0&15, bit4=row any-spike
__device__ int           g_uniform;      // 1 if id nibbles are 128-periodic (fast path valid)

// ---------------------------------------------------------------------------
// Pre: check whether id nibbles are 128-periodic (enables per-thread-constant
// nibble fast path in k_rowacc).
// ---------------------------------------------------------------------------
__global__ void k_pre(const int* __restrict__ ids) {
    int tid = threadIdx.x;
    if (tid == 0) g_uniform = 1;
    __syncthreads();
    int ok = 1;
    for (int i = tid; i < NIN; i += blockDim.x)
        if ((__ldg(&ids[i]) & 15) != (__ldg(&ids[i & 127]) & 15)) ok = 0;
    if (!ok) atomicAnd(&g_uniform, 0);
}

// ---------------------------------------------------------------------------
// Memory-bound frame scan: one warp per (b,t) row (2312 int32 = 9248B).
// Per-thread parity accumulation (no ballots -> free load batching / high MLP),
// single REDUX xor/or per row. Writes packed byte, transposed for the scan.
// ---------------------------------------------------------------------------
__global__ void __launch_bounds__(256) k_rowacc(const int* __restrict__ frames,
                                                const int* __restrict__ ids) {
    int wid  = (blockIdx.x * blockDim.x + threadIdx.x) >> 5;   // row = b*T + t
    int lane = threadIdx.x & 31;

    const int4* row4 = reinterpret_cast<const int4*>(frames + (size_t)wid * NIN);
    unsigned acc, anyv;

    if (g_uniform) {
        // Per-slot nibbles: element i = g*128 + 4*lane + e, nibble constant in g.
        int4 idv = __ldg(&reinterpret_cast<const int4*>(ids)[lane]);
        unsigned n0 = idv.x & 15, n1 = idv.y & 15, n2 = idv.z & 15, n3 = idv.w & 15;
        unsigned p0 = 0, p1 = 0, p2 = 0, p3 = 0, am = 0;
        #pragma unroll 6
        for (int g = 0; g < NFULL; g++) {
            int4 v = __ldg(&row4[g * 32 + lane]);
            p0 ^= (v.x != 0); p1 ^= (v.y != 0);
            p2 ^= (v.z != 0); p3 ^= (v.w != 0);
            am |= (unsigned)(v.x | v.y | v.z | v.w);
        }
        if (lane < NTAIL) {   // tail chunks; base 18*128=2304 ≡ 0 mod 16 -> same nibbles
            int4 v = __ldg(&row4[NFULL * 32 + lane]);
            p0 ^= (v.x != 0); p1 ^= (v.y != 0);
            p2 ^= (v.z != 0); p3 ^= (v.w != 0);
            am |= (unsigned)(v.x | v.y | v.z | v.w);
        }
        unsigned a = (p0 ? n0 : 0u) ^ (p1 ? n1 : 0u) ^ (p2 ? n2 : 0u) ^ (p3 ? n3 : 0u);
        acc  = __reduce_xor_sync(0xFFFFFFFFu, a);
        anyv = __reduce_or_sync(0xFFFFFFFFu, am);
    } else {
        // Correct general fallback (never taken for the actual data)
        const int* rowp = frames + (size_t)wid * NIN;
        unsigned x = 0, any = 0;
        for (int i = lane; i < NIN; i += 32) {
            int v = __ldg(&rowp[i]);
            if (v) { x ^= (unsigned)(__ldg(&ids[i]) & 15); any = 1u; }
        }
        acc  = __reduce_xor_sync(0xFFFFFFFFu, x);
        anyv = __reduce_or_sync(0xFFFFFFFFu, any);
    }

    if (lane == 0) {
        int b = wid >> 7, t = wid & 127;
        g_accAnyT[t * 128 + b] =
            (unsigned char)((acc & 15u) | (anyv ? 16u : 0u));
    }
}

// ---------------------------------------------------------------------------
// Fused scan + epilogue. Each of NB_FUSED blocks redundantly performs the
// cheap scan (A1 table, has[t]/dt[t], per-batch 4-bit recurrences, 16-bin
// histograms) entirely in smem, then writes its disjoint slice of the output
// (spikes [BT,10], d0 [2048,16], d1 [10,16]).
// ---------------------------------------------------------------------------
__global__ void __launch_bounds__(256) k_fused(float*       __restrict__ out,
                                               const int*   __restrict__ nid0,
                                               const float* __restrict__ vth0,
                                               const float* __restrict__ map0,
                                               const float* __restrict__ map1,
                                               const float* __restrict__ vth1) {
    __shared__ unsigned char sAcc[BT];      // 16KB: accAnyT copy
    __shared__ unsigned char sS1[BT];       // 16KB: s1 per (t*128+b), 0xFF = inactive
    __shared__ int           sA1[16];
    __shared__ int           sc0[16], sc1[16];
    __shared__ unsigned char sHas[T_DIM], sDt[T_DIM];

    int tid = threadIdx.x;

    // Coalesced copy of accAnyT into smem
    {
        uint4*       dst = reinterpret_cast<uint4*>(sAcc);
        const uint4* src = reinterpret_cast<const uint4*>(g_accAnyT);
        for (int i = tid; i < BT / 16; i += 256) dst[i] = src[i];
    }
    if (tid < 16) { sA1[tid] = 0; sc0[tid] = 0; sc1[tid] = 0; }
    __syncthreads();

    // A1[p] = XOR_{j: mem_map0[j,p] >= v_th0[j]} neuron_id0[j]
    {
        int loc[16];
        #pragma unroll
        for (int p = 0; p < 16; p++) loc[p] = 0;
        for (int j = tid; j < NHID; j += 256) {
            int   nid = __ldg(&nid0[j]);
            float vt  = __ldg(&vth0[j]);
            const float4* r = reinterpret_cast<const float4*>(map0 + (size_t)j * 16);
            #pragma unroll
            for (int q = 0; q < 4; q++) {
                float4 mv = __ldg(&r[q]);
                if (mv.x >= vt) loc[q * 4 + 0] ^= nid;
                if (mv.y >= vt) loc[q * 4 + 1] ^= nid;
                if (mv.z >= vt) loc[q * 4 + 2] ^= nid;
                if (mv.w >= vt) loc[q * 4 + 3] ^= nid;
            }
        }
        #pragma unroll
        for (int p = 0; p < 16; p++)
            if (loc[p]) atomicXor(&sA1[p], loc[p]);
    }

    // has[t]: OR over batch (bit4 of each byte), bank-stagger to avoid conflicts
    if (tid < T_DIM) {
        const unsigned* w = reinterpret_cast<const unsigned*>(sAcc) + tid * 32;
        unsigned o = 0;
        #pragma unroll
        for (int k = 0; k < 32; k++) o |= w[(k + tid) & 31];
        sHas[tid] = (o & 0x10101010u) ? 1 : 0;
    }
    __syncthreads();

    // delta_t sequence (t_last is effectively a global scalar in the reference)
    if (tid == 0) {
        int tl = 0;
        for (int t = 0; t < T_DIM; t++) {
            if (sHas[t]) { sDt[t] = (unsigned char)((t - tl) & 15); tl = t; }
            else         { sDt[t] = 0; }
        }
    }
    __syncthreads();

    // Per-batch 4-bit state scan + packed-byte histograms (thread b < 128)
    if (tid < B_DIM) {
        int s0 = 0, s1 = 0;
        unsigned long long h0lo = 0, h0hi = 0, h1lo = 0, h1hi = 0;
        for (int t = 0; t < T_DIM; t++) {
            if (sHas[t]) {
                int dt = sDt[t];
                int a  = sAcc[t * 128 + tid] & 15;
                s0 ^= dt ^ a;
                {
                    unsigned long long inc = 1ULL << ((s0 & 7) * 8);
                    if (s0 < 8) h0lo += inc; else h0hi += inc;
                }
                int a1 = sA1[s0] & 15;
                s1 ^= dt ^ a1;
                {
                    unsigned long long inc = 1ULL << ((s1 & 7) * 8);
                    if (s1 < 8) h1lo += inc; else h1hi += inc;
                }
                sS1[t * 128 + tid] = (unsigned char)s1;
            } else {
                sS1[t * 128 + tid] = 0xFF;
            }
        }
        #pragma unroll
        for (int p = 0; p < 8; p++) {
            int c;
            c = (int)((h0lo >> (p * 8)) & 255u); if (c) atomicAdd(&sc0[p],     c);
            c = (int)((h0hi >> (p * 8)) & 255u); if (c) atomicAdd(&sc0[p + 8], c);
            c = (int)((h1lo >> (p * 8)) & 255u); if (c) atomicAdd(&sc1[p],     c);
            c = (int)((h1hi >> (p * 8)) & 255u); if (c) atomicAdd(&sc1[p + 8], c);
        }
    }
    __syncthreads();

    // Write this block's slice of the output
    int start = blockIdx.x * CHUNK;
    int end   = start + CHUNK; if (end > TOT_OUT) end = TOT_OUT;
    for (int e = start + tid; e < end; e += 256) {
        float r;
        if (e < NS_OUT) {
            int bt = e / NOUT;
            int k  = e - bt * NOUT;
            int s  = sS1[(bt & 127) * 128 + (bt >> 7)];
            r = 0.0f;
            if (s != 0xFF)
                r = (__ldg(&map1[k * 16 + s]) >= __ldg(&vth1[k])) ? 1.0f : 0.0f;
        } else if (e < NS_OUT + NHID * 16) {
            int f = e - NS_OUT;
            int p = f & 15;
            r = ALPHA_F * (float)sc0[p] * ((float)p - __ldg(&map0[f]));
        } else {
            int f = e - NS_OUT - NHID * 16;
            int p = f & 15;
            r = ALPHA_F * (float)sc1[p] * ((float)p - __ldg(&map1[f]));
        }
        out[e] = r;
    }
}

// ---------------------------------------------------------------------------
// Inputs (metadata order): frames, input_neuron_id, tau0, v_th0, neuron_id0,
// mem_map0, syn_w0, tau1, v_th1, neuron_id1, mem_map1, syn_w1
// ---------------------------------------------------------------------------
extern "C" void kernel_launch(void* const* d_in, const int* in_sizes, int n_in,
                              void* d_out, int out_size) {
    const int*   frames = (const int*)  d_in[0];
    const int*   inid   = (const int*)  d_in[1];
    const float* vth0   = (const float*)d_in[3];
    const int*   nid0   = (const int*)  d_in[4];
    const float* map0   = (const float*)d_in[5];
    const float* vth1   = (const float*)d_in[8];
    const float* map1   = (const float*)d_in[10];

    k_pre<<<1, 256>>>(inid);
    k_rowacc<<<BT * 32 / 256, 256>>>(frames, inid);
    k_fused<<<NB_FUSED, 256>>>((float*)d_out, nid0, vth0, map0, map1, vth1);
}

// round 3
// speedup vs baseline: 1.3558x; 1.1980x over previous
#include <cuda_runtime.h>

// Problem constants (fixed shapes for SNNModel_67611375174158)
#define B_DIM   128
#define T_DIM   128
#define BT      (B_DIM * T_DIM)          // 16384 rows
#define NIN     2312                     // 2*34*34
#define NCH     (NIN / 4)                // 578 int4 chunks per row
#define NFULL   (NCH / 32)               // 18 full 32-chunk groups
#define NTAIL   (NCH - NFULL * 32)       // 2 tail chunks
#define NHID    2048
#define NOUT    10
#define ALPHA_F 0.001f

#define NS_OUT  (BT * NOUT)                       // 163840 spike floats
#define TOT_OUT (NS_OUT + NHID * 16 + NOUT * 16)  // 196768 total floats
#define NB_FUSED 32
#define CHUNK   (TOT_OUT / NB_FUSED)              // 6149 exact (32*6149=196768)

#define NROWBLK (BT / 8)                          // 2048 row blocks (8 warps each)

// Scratch (no allocations allowed -> __device__ globals)
__device__ unsigned char g_accAnyT[BT];  // [t*128+b]: bits[3:0]=acc&15, bit4=row any-spike
__device__ int           g_A1[16];       // layer-1 XOR table

// ---------------------------------------------------------------------------
// Frame scan: one warp per (b,t) row (2312 int32 = 9248B, fully general ids).
// Per-thread masked-XOR accumulation; ids (9KB) are L1-resident so the second
// load stream is free relative to the DRAM-bound frames stream (__ldcs,
// streaming / evict-first). One REDUX xor + or per row.
// Block NROWBLK (extra block) builds the A1 table concurrently.
// ---------------------------------------------------------------------------
__global__ void __launch_bounds__(256) k_rowacc(const int*   __restrict__ frames,
                                                const int*   __restrict__ ids,
                                                const int*   __restrict__ nid0,
                                                const float* __restrict__ vth0,
                                                const float* __restrict__ map0) {
    if (blockIdx.x == NROWBLK) {
        // A1[p] = XOR_{j: mem_map0[j,p] >= v_th0[j]} neuron_id0[j]
        __shared__ int sA1[16];
        int tid = threadIdx.x;
        if (tid < 16) sA1[tid] = 0;
        __syncthreads();
        int loc[16];
        #pragma unroll
        for (int p = 0; p < 16; p++) loc[p] = 0;
        for (int j = tid; j < NHID; j += 256) {
            int   nid = __ldg(&nid0[j]);
            float vt  = __ldg(&vth0[j]);
            const float4* r = reinterpret_cast<const float4*>(map0 + (size_t)j * 16);
            #pragma unroll
            for (int q = 0; q < 4; q++) {
                float4 mv = __ldg(&r[q]);
                if (mv.x >= vt) loc[q * 4 + 0] ^= nid;
                if (mv.y >= vt) loc[q * 4 + 1] ^= nid;
                if (mv.z >= vt) loc[q * 4 + 2] ^= nid;
                if (mv.w >= vt) loc[q * 4 + 3] ^= nid;
            }
        }
        #pragma unroll
        for (int p = 0; p < 16; p++)
            if (loc[p]) atomicXor(&sA1[p], loc[p]);
        __syncthreads();
        if (tid < 16) g_A1[tid] = sA1[tid];
        return;
    }

    int wid  = (blockIdx.x * 256 + threadIdx.x) >> 5;   // row = b*T + t
    int lane = threadIdx.x & 31;

    const int4* row4 = reinterpret_cast<const int4*>(frames + (size_t)wid * NIN);
    const int4* ids4 = reinterpret_cast<const int4*>(ids);

    unsigned x = 0, any = 0;
    #pragma unroll 6
    for (int g = 0; g < NFULL; g++) {
        int4 v  = __ldcs(&row4[g * 32 + lane]);
        int4 id = __ldg(&ids4[g * 32 + lane]);
        if (v.x) x ^= (unsigned)id.x & 15u;
        if (v.y) x ^= (unsigned)id.y & 15u;
        if (v.z) x ^= (unsigned)id.z & 15u;
        if (v.w) x ^= (unsigned)id.w & 15u;
        any |= (unsigned)(v.x | v.y | v.z | v.w);
    }
    if (lane < NTAIL) {
        int4 v  = __ldcs(&row4[NFULL * 32 + lane]);
        int4 id = __ldg(&ids4[NFULL * 32 + lane]);
        if (v.x) x ^= (unsigned)id.x & 15u;
        if (v.y) x ^= (unsigned)id.y & 15u;
        if (v.z) x ^= (unsigned)id.z & 15u;
        if (v.w) x ^= (unsigned)id.w & 15u;
        any |= (unsigned)(v.x | v.y | v.z | v.w);
    }

    unsigned acc  = __reduce_xor_sync(0xFFFFFFFFu, x);
    unsigned anyv = __reduce_or_sync(0xFFFFFFFFu, any);

    if (lane == 0) {
        int b = wid >> 7, t = wid & 127;
        g_accAnyT[t * 128 + b] =
            (unsigned char)((acc & 15u) | (anyv ? 16u : 0u));
    }
}

// ---------------------------------------------------------------------------
// Fused scan + epilogue. Each of NB_FUSED blocks redundantly performs the
// cheap scan (has[t]/dt[t], per-batch 4-bit recurrences, 16-bin histograms)
// entirely in smem, then writes its disjoint slice of the output
// (spikes [BT,10], d0 [2048,16], d1 [10,16]).
// ---------------------------------------------------------------------------
__global__ void __launch_bounds__(256) k_fused(float*       __restrict__ out,
                                               const float* __restrict__ map0,
                                               const float* __restrict__ map1,
                                               const float* __restrict__ vth1) {
    __shared__ unsigned char sAcc[BT];      // 16KB: accAnyT copy
    __shared__ unsigned char sS1[BT];       // 16KB: s1 per (t*128+b), 0xFF = inactive
    __shared__ int           sA1[16];
    __shared__ int           sc0[16], sc1[16];
    __shared__ unsigned char sHas[T_DIM], sDt[T_DIM];

    int tid = threadIdx.x;

    // Coalesced copy of accAnyT into smem + A1 table load
    {
        uint4*       dst = reinterpret_cast<uint4*>(sAcc);
        const uint4* src = reinterpret_cast<const uint4*>(g_accAnyT);
        for (int i = tid; i < BT / 16; i += 256) dst[i] = src[i];
    }
    if (tid < 16) { sA1[tid] = g_A1[tid]; sc0[tid] = 0; sc1[tid] = 0; }
    __syncthreads();

    // has[t]: OR over batch (bit4 of each byte), bank-stagger to avoid conflicts
    if (tid < T_DIM) {
        const unsigned* w = reinterpret_cast<const unsigned*>(sAcc) + tid * 32;
        unsigned o = 0;
        #pragma unroll
        for (int k = 0; k < 32; k++) o |= w[(k + tid) & 31];
        sHas[tid] = (o & 0x10101010u) ? 1 : 0;
    }
    __syncthreads();

    // delta_t sequence (t_last is effectively a global scalar in the reference)
    if (tid == 0) {
        int tl = 0;
        for (int t = 0; t < T_DIM; t++) {
            if (sHas[t]) { sDt[t] = (unsigned char)((t - tl) & 15); tl = t; }
            else         { sDt[t] = 0; }
        }
    }
    __syncthreads();

    // Per-batch 4-bit state scan + packed-byte histograms (thread b < 128)
    if (tid < B_DIM) {
        int s0 = 0, s1 = 0;
        unsigned long long h0lo = 0, h0hi = 0, h1lo = 0, h1hi = 0;
        for (int t = 0; t < T_DIM; t++) {
            if (sHas[t]) {
                int dt = sDt[t];
                int a  = sAcc[t * 128 + tid] & 15;
                s0 ^= dt ^ a;
                {
                    unsigned long long inc = 1ULL << ((s0 & 7) * 8);
                    if (s0 < 8) h0lo += inc; else h0hi += inc;
                }
                int a1 = sA1[s0] & 15;
                s1 ^= dt ^ a1;
                {
                    unsigned long long inc = 1ULL << ((s1 & 7) * 8);
                    if (s1 < 8) h1lo += inc; else h1hi += inc;
                }
                sS1[t * 128 + tid] = (unsigned char)s1;
            } else {
                sS1[t * 128 + tid] = 0xFF;
            }
        }
        #pragma unroll
        for (int p = 0; p < 8; p++) {
            int c;
            c = (int)((h0lo >> (p * 8)) & 255u); if (c) atomicAdd(&sc0[p],     c);
            c = (int)((h0hi >> (p * 8)) & 255u); if (c) atomicAdd(&sc0[p + 8], c);
            c = (int)((h1lo >> (p * 8)) & 255u); if (c) atomicAdd(&sc1[p],     c);
            c = (int)((h1hi >> (p * 8)) & 255u); if (c) atomicAdd(&sc1[p + 8], c);
        }
    }
    __syncthreads();

    // Write this block's slice of the output
    int start = blockIdx.x * CHUNK;
    int end   = start + CHUNK;
    for (int e = start + tid; e < end; e += 256) {
        float r;
        if (e < NS_OUT) {
            int bt = e / NOUT;
            int k  = e - bt * NOUT;
            int s  = sS1[(bt & 127) * 128 + (bt >> 7)];
            r = 0.0f;
            if (s != 0xFF)
                r = (__ldg(&map1[k * 16 + s]) >= __ldg(&vth1[k])) ? 1.0f : 0.0f;
        } else if (e < NS_OUT + NHID * 16) {
            int f = e - NS_OUT;
            int p = f & 15;
            r = ALPHA_F * (float)sc0[p] * ((float)p - __ldg(&map0[f]));
        } else {
            int f = e - NS_OUT - NHID * 16;
            int p = f & 15;
            r = ALPHA_F * (float)sc1[p] * ((float)p - __ldg(&map1[f]));
        }
        out[e] = r;
    }
}

// ---------------------------------------------------------------------------
// Inputs (metadata order): frames, input_neuron_id, tau0, v_th0, neuron_id0,
// mem_map0, syn_w0, tau1, v_th1, neuron_id1, mem_map1, syn_w1
// ---------------------------------------------------------------------------
extern "C" void kernel_launch(void* const* d_in, const int* in_sizes, int n_in,
                              void* d_out, int out_size) {
    const int*   frames = (const int*)  d_in[0];
    const int*   inid   = (const int*)  d_in[1];
    const float* vth0   = (const float*)d_in[3];
    const int*   nid0   = (const int*)  d_in[4];
    const float* map0   = (const float*)d_in[5];
    const float* vth1   = (const float*)d_in[8];
    const float* map1   = (const float*)d_in[10];

    k_rowacc<<<NROWBLK + 1, 256>>>(frames, inid, nid0, vth0, map0);
    k_fused<<<NB_FUSED, 256>>>((float*)d_out, map0, map1, vth1);
}

// round 4
// speedup vs baseline: 1.4724x; 1.0860x over previous
#include <cuda_runtime.h>

// Problem constants (fixed shapes for SNNModel_67611375174158)
#define B_DIM   128
#define T_DIM   128
#define BT      (B_DIM * T_DIM)          // 16384 rows
#define NIN     2312                     // 2*34*34
#define NCH     (NIN / 4)                // 578 int4 chunks per row
#define NFULL   (NCH / 32)               // 18 full 32-chunk groups
#define NTAIL   (NCH - NFULL * 32)       // 2 tail chunks
#define NHID    2048
#define NOUT    10
#define ALPHA_F 0.001f

#define NS_OUT  (BT * NOUT)                       // 163840 spike floats
#define TOT_OUT (NS_OUT + NHID * 16 + NOUT * 16)  // 196768 total floats
#define NB_FUSED 32
#define CHUNK   (TOT_OUT / NB_FUSED)              // 6149 exact

#define NROWBLK (BT / 8)                          // 2048 row blocks (8 warps each)

// Scratch (no allocations allowed -> __device__ globals)
__device__ unsigned char g_accAnyT[BT];  // [t*128+b]: bits[3:0]=acc&15, bit4=any-spike
__device__ int           g_A1[16];       // layer-1 XOR table

// ---------------------------------------------------------------------------
// Frame scan: one warp per (b,t) row. Default cache policy (L2 keeps most of
// frames resident across graph replays -> effective BW above DRAM roofline).
// Extra block builds the A1 table concurrently.
// ---------------------------------------------------------------------------
__global__ void __launch_bounds__(256) k_rowacc(const int*   __restrict__ frames,
                                                const int*   __restrict__ ids,
                                                const int*   __restrict__ nid0,
                                                const float* __restrict__ vth0,
                                                const float* __restrict__ map0) {
    if (blockIdx.x == NROWBLK) {
        __shared__ int sA1[16];
        int tid = threadIdx.x;
        if (tid < 16) sA1[tid] = 0;
        __syncthreads();
        int loc[16];
        #pragma unroll
        for (int p = 0; p < 16; p++) loc[p] = 0;
        for (int j = tid; j < NHID; j += 256) {
            int   nid = __ldg(&nid0[j]);
            float vt  = __ldg(&vth0[j]);
            const float4* r = reinterpret_cast<const float4*>(map0 + (size_t)j * 16);
            #pragma unroll
            for (int q = 0; q < 4; q++) {
                float4 mv = __ldg(&r[q]);
                if (mv.x >= vt) loc[q * 4 + 0] ^= nid;
                if (mv.y >= vt) loc[q * 4 + 1] ^= nid;
                if (mv.z >= vt) loc[q * 4 + 2] ^= nid;
                if (mv.w >= vt) loc[q * 4 + 3] ^= nid;
            }
        }
        #pragma unroll
        for (int p = 0; p < 16; p++)
            if (loc[p]) atomicXor(&sA1[p], loc[p]);
        __syncthreads();
        if (tid < 16) g_A1[tid] = sA1[tid];
        return;
    }

    int wid  = (blockIdx.x * 256 + threadIdx.x) >> 5;   // row = b*T + t
    int lane = threadIdx.x & 31;

    const int4* row4 = reinterpret_cast<const int4*>(frames + (size_t)wid * NIN);
    const int4* ids4 = reinterpret_cast<const int4*>(ids);

    unsigned x = 0, any = 0;
    #pragma unroll 6
    for (int g = 0; g < NFULL; g++) {
        int4 v  = __ldg(&row4[g * 32 + lane]);
        int4 id = __ldg(&ids4[g * 32 + lane]);
        if (v.x) x ^= (unsigned)id.x & 15u;
        if (v.y) x ^= (unsigned)id.y & 15u;
        if (v.z) x ^= (unsigned)id.z & 15u;
        if (v.w) x ^= (unsigned)id.w & 15u;
        any |= (unsigned)(v.x | v.y | v.z | v.w);
    }
    if (lane < NTAIL) {
        int4 v  = __ldg(&row4[NFULL * 32 + lane]);
        int4 id = __ldg(&ids4[NFULL * 32 + lane]);
        if (v.x) x ^= (unsigned)id.x & 15u;
        if (v.y) x ^= (unsigned)id.y & 15u;
        if (v.z) x ^= (unsigned)id.z & 15u;
        if (v.w) x ^= (unsigned)id.w & 15u;
        any |= (unsigned)(v.x | v.y | v.z | v.w);
    }

    unsigned acc  = __reduce_xor_sync(0xFFFFFFFFu, x);
    unsigned anyv = __reduce_or_sync(0xFFFFFFFFu, any);

    if (lane == 0) {
        int b = wid >> 7, t = wid & 127;
        g_accAnyT[t * 128 + b] =
            (unsigned char)((acc & 15u) | (anyv ? 16u : 0u));
    }
}

// ---------------------------------------------------------------------------
// Fused scan + epilogue, branch-free. Each of NB_FUSED blocks redundantly
// performs the scan in smem, then writes its disjoint slice of the output.
// ---------------------------------------------------------------------------
__global__ void __launch_bounds__(256) k_fused(float*       __restrict__ out,
                                               const float* __restrict__ map0,
                                               const float* __restrict__ map1,
                                               const float* __restrict__ vth1) {
    __shared__ unsigned char sAcc[BT];      // 16KB: accAnyT copy [t*128+b]
    __shared__ unsigned char sS1[BT];       // 16KB: s1 [t*128+b], 0xFF = inactive
    __shared__ int           sA1[16];
    __shared__ int           sc0[16], sc1[16];
    __shared__ unsigned      sSpk[16];      // spike bitmask per s (10 bits over k)
    __shared__ unsigned      sM[4];         // 128-bit active-timestep mask
    __shared__ unsigned char sDtA[T_DIM];   // dt | (active<<4)

    int tid  = threadIdx.x;
    int lane = tid & 31;

    // Phase A: copy accAnyT into smem; init tables
    {
        uint4*       dst = reinterpret_cast<uint4*>(sAcc);
        const uint4* src = reinterpret_cast<const uint4*>(g_accAnyT);
        for (int i = tid; i < BT / 16; i += 256) dst[i] = src[i];
    }
    if (tid < 16) { sA1[tid] = g_A1[tid]; sc0[tid] = 0; sc1[tid] = 0; sSpk[tid] = 0; }
    __syncthreads();

    // Phase B: tid<128 -> has[t] + 128-bit mask via ballot.
    //          tid>=128 -> build spike bitmask table concurrently.
    if (tid < 128) {
        const unsigned* w = reinterpret_cast<const unsigned*>(sAcc) + tid * 32;
        unsigned o = 0;
        #pragma unroll
        for (int k = 0; k < 32; k++) o |= w[(k + tid) & 31];
        int has = (o & 0x10101010u) ? 1 : 0;
        unsigned bal = __ballot_sync(0xFFFFFFFFu, has);
        if (lane == 0) sM[tid >> 5] = bal;
    } else {
        for (int q = tid - 128; q < 160; q += 128) {
            int k = q >> 4, s = q & 15;
            if (__ldg(&map1[k * 16 + s]) >= __ldg(&vth1[k]))
                atomicOr(&sSpk[s], 1u << k);
        }
    }
    __syncthreads();

    // Phase C: per-t delta_t from previous active timestep (parallel, clz-based)
    if (tid < 128) {
        int t = tid;
        int word = t >> 5, bit = t & 31;
        int active = (sM[word] >> bit) & 1;
        unsigned m = bit ? (sM[word] & ((1u << bit) - 1u)) : 0u;
        int tl = 0;
        int w = word;
        while (true) {
            if (m) { tl = (w << 5) + 31 - __clz(m); break; }
            if (--w < 0) break;
            m = sM[w];
        }
        int dt = active ? ((t - tl) & 15) : 0;
        sDtA[t] = (unsigned char)(dt | (active << 4));
    }
    __syncthreads();

    // Phase D: branch-free per-batch 4-bit scan (thread b < 128)
    if (tid < 128) {
        int b = tid;
        int s0 = 0, s1 = 0;
        unsigned long long h0lo = 0, h0hi = 0, h1lo = 0, h1hi = 0;
        #pragma unroll 8
        for (int t = 0; t < T_DIM; t++) {
            int da   = sDtA[t];
            int act  = da >> 4;                 // 0/1
            int dt   = da & 15;
            int am   = act ? 15 : 0;
            int a    = sAcc[t * 128 + b] & am;
            s0 ^= dt ^ a;
            unsigned long long inc0 = act ? (1ULL << ((s0 & 7) * 8)) : 0ULL;
            h0lo += (s0 < 8) ? inc0 : 0ULL;
            h0hi += (s0 < 8) ? 0ULL : inc0;
            int a1 = sA1[s0] & am;
            s1 ^= dt ^ a1;
            unsigned long long inc1 = act ? (1ULL << ((s1 & 7) * 8)) : 0ULL;
            h1lo += (s1 < 8) ? inc1 : 0ULL;
            h1hi += (s1 < 8) ? 0ULL : inc1;
            sS1[t * 128 + b] = (unsigned char)(act ? s1 : 0xFF);
        }

        // Expand byte-packed counters to 16-bit lanes, warp-reduce, 16-lane add.
        const unsigned long long EM = 0x00FF00FF00FF00FFULL;
        unsigned long long e0 = h0lo & EM,        e1 = (h0lo >> 8) & EM;
        unsigned long long e2 = h0hi & EM,        e3 = (h0hi >> 8) & EM;
        unsigned long long f0 = h1lo & EM,        f1 = (h1lo >> 8) & EM;
        unsigned long long f2 = h1hi & EM,        f3 = (h1hi >> 8) & EM;
        #pragma unroll
        for (int o = 16; o; o >>= 1) {
            e0 += __shfl_xor_sync(0xFFFFFFFFu, e0, o);
            e1 += __shfl_xor_sync(0xFFFFFFFFu, e1, o);
            e2 += __shfl_xor_sync(0xFFFFFFFFu, e2, o);
            e3 += __shfl_xor_sync(0xFFFFFFFFu, e3, o);
            f0 += __shfl_xor_sync(0xFFFFFFFFu, f0, o);
            f1 += __shfl_xor_sync(0xFFFFFFFFu, f1, o);
            f2 += __shfl_xor_sync(0xFFFFFFFFu, f2, o);
            f3 += __shfl_xor_sync(0xFFFFFFFFu, f3, o);
        }
        if (lane < 16) {
            int slot = (lane & 7) >> 1;
            unsigned long long c0 = (lane & 1) ? ((lane >= 8) ? e3 : e1)
                                               : ((lane >= 8) ? e2 : e0);
            unsigned long long c1 = (lane & 1) ? ((lane >= 8) ? f3 : f1)
                                               : ((lane >= 8) ? f2 : f0);
            atomicAdd(&sc0[lane], (int)((c0 >> (slot * 16)) & 0xFFFFu));
            atomicAdd(&sc1[lane], (int)((c1 >> (slot * 16)) & 0xFFFFu));
        }
    }
    __syncthreads();

    // Phase F: write this block's slice of the output
    int start = blockIdx.x * CHUNK;
    int end   = start + CHUNK;
    for (int e = start + tid; e < end; e += 256) {
        float r;
        if (e < NS_OUT) {
            int bt = e / NOUT;
            int k  = e - bt * NOUT;
            int s  = sS1[(bt & 127) * 128 + (bt >> 7)];
            unsigned msk = sSpk[s & 15];
            r = (s != 0xFF && ((msk >> k) & 1u)) ? 1.0f : 0.0f;
        } else if (e < NS_OUT + NHID * 16) {
            int f = e - NS_OUT;
            int p = f & 15;
            r = ALPHA_F * (float)sc0[p] * ((float)p - __ldg(&map0[f]));
        } else {
            int f = e - NS_OUT - NHID * 16;
            int p = f & 15;
            r = ALPHA_F * (float)sc1[p] * ((float)p - __ldg(&map1[f]));
        }
        out[e] = r;
    }
}

// ---------------------------------------------------------------------------
// Inputs (metadata order): frames, input_neuron_id, tau0, v_th0, neuron_id0,
// mem_map0, syn_w0, tau1, v_th1, neuron_id1, mem_map1, syn_w1
// ---------------------------------------------------------------------------
extern "C" void kernel_launch(void* const* d_in, const int* in_sizes, int n_in,
                              void* d_out, int out_size) {
    const int*   frames = (const int*)  d_in[0];
    const int*   inid   = (const int*)  d_in[1];
    const float* vth0   = (const float*)d_in[3];
    const int*   nid0   = (const int*)  d_in[4];
    const float* map0   = (const float*)d_in[5];
    const float* vth1   = (const float*)d_in[8];
    const float* map1   = (const float*)d_in[10];

    k_rowacc<<<NROWBLK + 1, 256>>>(frames, inid, nid0, vth0, map0);
    k_fused<<<NB_FUSED, 256>>>((float*)d_out, map0, map1, vth1);
}